// round 4
// baseline (speedup 1.0000x reference)
#include <cuda_runtime.h>
#include <cuda_fp16.h>
#include <math.h>

#define NN_MAX 100000
#define EE_MAX 1600000
#define DH 64

// ---------------- device scratch ----------------
__device__ __half g_tmph[NN_MAX * DH]; // fp16 messages: (act(X) @ W^T) * dinv
__device__ float g_h[NN_MAX * DH];     // layer activations (pre-BN, post-bias)
__device__ float g_dinv[NN_MAX];
__device__ int   g_counts[NN_MAX];     // zeroed by scan3 after use (self-restoring)
__device__ int   g_rowptr[NN_MAX + 1];
__device__ int   g_cursor[NN_MAX];
__device__ int   g_esrc[EE_MAX];
__device__ int   g_blocksums[128];
__device__ float g_sums[DH];           // zeroed by stats_final after use
__device__ float g_sumsq[DH];
__device__ float g_scale[DH];
__device__ float g_shift[DH];

__device__ __forceinline__ float gelu_f(float v) {
    return 0.5f * v * (1.0f + erff(v * 0.70710678118654752440f));
}

// ---------------- CSR build ----------------
__global__ void hist_kernel(const int* __restrict__ dst, int ee) {
    int e = blockIdx.x * blockDim.x + threadIdx.x;
    if (e < ee) atomicAdd(&g_counts[dst[e]], 1);
}

// block-wise inclusive scan of g_counts -> g_rowptr, block totals -> g_blocksums
__global__ void scan1_kernel(int nn) {
    __shared__ int s[1024];
    int t = threadIdx.x;
    int i = blockIdx.x * 1024 + t;
    int c = (i < nn) ? g_counts[i] : 0;
    s[t] = c;
    __syncthreads();
    for (int off = 1; off < 1024; off <<= 1) {
        int v = (t >= off) ? s[t - off] : 0;
        __syncthreads();
        s[t] += v;
        __syncthreads();
    }
    if (i < nn) g_rowptr[i] = s[t];
    if (t == 1023) g_blocksums[blockIdx.x] = s[1023];
}

// merged scan2+scan3: each block redundantly scans the block partials,
// finalizes rowptr/cursor/dinv, and zeroes counts for the next call.
__global__ void scan3_kernel(int nn, int ee, int nb) {
    __shared__ int bs[128];
    int t = threadIdx.x;
    if (t < 128) bs[t] = (t < nb) ? g_blocksums[t] : 0;
    __syncthreads();
    for (int off = 1; off < 128; off <<= 1) {
        int v = (t >= off && t < 128) ? bs[t - off] : 0;
        __syncthreads();
        if (t < 128) bs[t] += v;
        __syncthreads();
    }
    int base = (blockIdx.x == 0) ? 0 : bs[blockIdx.x - 1];

    int i = blockIdx.x * 1024 + t;
    if (i < nn) {
        int c = g_counts[i];
        g_counts[i] = 0;                 // restore invariant for next call
        int excl = g_rowptr[i] - c + base;
        g_rowptr[i] = excl;
        g_cursor[i] = excl;
        g_dinv[i] = rsqrtf((float)(c + 1));  // +1 self loop
    }
    if (i == 0) g_rowptr[nn] = ee;
}

__global__ void fill_kernel(const int* __restrict__ src, const int* __restrict__ dst, int ee) {
    int e = blockIdx.x * blockDim.x + threadIdx.x;
    if (e < ee) {
        int pos = atomicAdd(&g_cursor[dst[e]], 1);
        g_esrc[pos] = src[e];
    }
}

// ---------------- GEMM: g_tmph[n,:] = fp16( (act(X)[n,:] @ W^T) * dinv[n] ) ----------------
// 64x64 tile per block, 256 threads, 4x4 register tile, BK=64.
template <int DIN, bool USE_GH, bool APPLY_ACT>
__global__ void gemm_scale_kernel(const float* __restrict__ Xin,
                                  const float* __restrict__ W, int nn) {
    const float* __restrict__ X = USE_GH ? (const float*)g_h : Xin;

    __shared__ float Xs[64 * 68];  // [k][n]
    __shared__ float Ws[64 * 68];  // [k][j]
    __shared__ float s_sc[DH];
    __shared__ float s_sh[DH];
    int tid = threadIdx.x;
    int br = blockIdx.x * 64;
    int tx = tid & 15;
    int ty = tid >> 4;

    if (APPLY_ACT) {
        if (tid < DH) { s_sc[tid] = g_scale[tid]; s_sh[tid] = g_shift[tid]; }
        __syncthreads();
    }

    float acc[4][4];
#pragma unroll
    for (int i = 0; i < 4; i++)
#pragma unroll
        for (int j = 0; j < 4; j++) acc[i][j] = 0.0f;

    for (int kb = 0; kb < DIN; kb += 64) {
#pragma unroll
        for (int i = tid; i < 4096; i += 256) {
            int n = i >> 6, k = i & 63;
            int row = br + n;
            float v = (row < nn) ? X[row * DIN + kb + k] : 0.0f;
            if (APPLY_ACT) v = gelu_f(v * s_sc[k] + s_sh[k]);
            Xs[k * 68 + n] = v;
        }
#pragma unroll
        for (int i = tid; i < 4096; i += 256) {
            int j = i >> 6, k = i & 63;
            Ws[k * 68 + j] = W[j * DIN + kb + k];
        }
        __syncthreads();
#pragma unroll 8
        for (int k = 0; k < 64; k++) {
            float4 a = *(const float4*)&Xs[k * 68 + ty * 4];
            float4 b = *(const float4*)&Ws[k * 68 + tx * 4];
            float av[4] = {a.x, a.y, a.z, a.w};
            float bv[4] = {b.x, b.y, b.z, b.w};
#pragma unroll
            for (int i = 0; i < 4; i++)
#pragma unroll
                for (int j = 0; j < 4; j++) acc[i][j] += av[i] * bv[j];
        }
        __syncthreads();
    }

#pragma unroll
    for (int i = 0; i < 4; i++) {
        int row = br + ty * 4 + i;
        if (row < nn) {
            float dv = g_dinv[row];
            __half2 p0 = __floats2half2_rn(acc[i][0] * dv, acc[i][1] * dv);
            __half2 p1 = __floats2half2_rn(acc[i][2] * dv, acc[i][3] * dv);
            uint2 u;
            u.x = *(unsigned int*)&p0;
            u.y = *(unsigned int*)&p1;
            *(uint2*)&g_tmph[row * DH + tx * 4] = u;
        }
    }
}

// ---------------- gather-aggregate + bias + BN stats ----------------
// warp per node; lane owns columns (2*lane, 2*lane+1) via half2. fp32 accumulate.
__global__ void gather_kernel(const float* __restrict__ bias, int nn) {
    __shared__ float ss[DH];
    __shared__ float sq[DH];
    int tid = threadIdx.x;
    if (tid < DH) { ss[tid] = 0.0f; sq[tid] = 0.0f; }
    __syncthreads();

    const __half2* __restrict__ tmp2 = (const __half2*)g_tmph;
    float2* __restrict__ h2 = (float2*)g_h;

    int lane = tid & 31;
    int warp = blockIdx.x * (blockDim.x >> 5) + (tid >> 5);
    int nwarps = gridDim.x * (blockDim.x >> 5);

    float bx = bias[2 * lane];
    float by = bias[2 * lane + 1];
    float s0 = 0.f, s1 = 0.f, q0 = 0.f, q1 = 0.f;

    for (int n = warp; n < nn; n += nwarps) {
        int st = g_rowptr[n];
        int en = g_rowptr[n + 1];
        float2 self = __half22float2(tmp2[n * 32 + lane]);
        float ax = self.x, ay = self.y;
        int e = st;
        for (; e + 8 <= en; e += 8) {
            int idx[8];
#pragma unroll
            for (int u = 0; u < 8; u++) idx[u] = g_esrc[e + u];
            __half2 v[8];
#pragma unroll
            for (int u = 0; u < 8; u++) v[u] = tmp2[idx[u] * 32 + lane];
            float2 f0 = __half22float2(v[0]);
            float2 f1 = __half22float2(v[1]);
            float2 f2 = __half22float2(v[2]);
            float2 f3 = __half22float2(v[3]);
            float2 f4 = __half22float2(v[4]);
            float2 f5 = __half22float2(v[5]);
            float2 f6 = __half22float2(v[6]);
            float2 f7 = __half22float2(v[7]);
            ax += ((f0.x + f1.x) + (f2.x + f3.x)) + ((f4.x + f5.x) + (f6.x + f7.x));
            ay += ((f0.y + f1.y) + (f2.y + f3.y)) + ((f4.y + f5.y) + (f6.y + f7.y));
        }
        for (; e < en; e++) {
            float2 f = __half22float2(tmp2[g_esrc[e] * 32 + lane]);
            ax += f.x; ay += f.y;
        }
        float dv = g_dinv[n];
        float rx = ax * dv + bx;
        float ry = ay * dv + by;
        h2[n * 32 + lane] = make_float2(rx, ry);
        s0 += rx; q0 += rx * rx;
        s1 += ry; q1 += ry * ry;
    }

    atomicAdd(&ss[2 * lane], s0);
    atomicAdd(&ss[2 * lane + 1], s1);
    atomicAdd(&sq[2 * lane], q0);
    atomicAdd(&sq[2 * lane + 1], q1);
    __syncthreads();
    if (tid < DH) {
        atomicAdd(&g_sums[tid], ss[tid]);
        atomicAdd(&g_sumsq[tid], sq[tid]);
    }
}

// ---------------- BN stats -> scale/shift; re-zero stats ----------------
__global__ void stats_final_kernel(const float* __restrict__ gamma,
                                   const float* __restrict__ beta, float invN) {
    int j = threadIdx.x;  // 64 threads
    float mean = g_sums[j] * invN;
    float var = g_sumsq[j] * invN - mean * mean;
    float sc = gamma[j] * rsqrtf(var + 1e-5f);
    g_scale[j] = sc;
    g_shift[j] = beta[j] - mean * sc;
    g_sums[j] = 0.0f;
    g_sumsq[j] = 0.0f;
}

// ---------------- final: out = act(h) @ Wf^T + bf  (64 -> 10) ----------------
__global__ void final_kernel(const float* __restrict__ Wf, const float* __restrict__ bf,
                             float* __restrict__ out, int nn) {
    __shared__ float Hs[64][65];
    __shared__ float Ws[10][64];
    __shared__ float s_sc[DH];
    __shared__ float s_sh[DH];
    int tid = threadIdx.x;  // 128 threads
    int br = blockIdx.x * 64;

    if (tid < DH) { s_sc[tid] = g_scale[tid]; s_sh[tid] = g_shift[tid]; }
    __syncthreads();

    for (int idx = tid; idx < 64 * 64; idx += 128) {
        int n = idx >> 6, k = idx & 63;
        int row = br + n;
        float v = (row < nn) ? g_h[row * DH + k] : 0.0f;
        Hs[n][k] = gelu_f(v * s_sc[k] + s_sh[k]);
    }
    for (int idx = tid; idx < 640; idx += 128) {
        Ws[idx >> 6][idx & 63] = Wf[idx];
    }
    __syncthreads();

    int nl = tid & 63;
    int c0 = (tid >> 6) * 5;
    float acc[5];
#pragma unroll
    for (int c = 0; c < 5; c++) acc[c] = bf[c0 + c];
#pragma unroll 16
    for (int k = 0; k < 64; k++) {
        float hv = Hs[nl][k];
#pragma unroll
        for (int c = 0; c < 5; c++) acc[c] += hv * Ws[c0 + c][k];
    }
    int row = br + nl;
    if (row < nn) {
#pragma unroll
        for (int c = 0; c < 5; c++) out[row * 10 + c0 + c] = acc[c];
    }
}

// ---------------- host orchestration ----------------
extern "C" void kernel_launch(void* const* d_in, const int* in_sizes, int n_in,
                              void* d_out, int out_size) {
    const float* x  = (const float*)d_in[0];
    const int*   ei = (const int*)d_in[1];
    const float* W1 = (const float*)d_in[2];
    const float* b1 = (const float*)d_in[3];
    const float* g1 = (const float*)d_in[4];
    const float* be1 = (const float*)d_in[5];
    const float* W2 = (const float*)d_in[6];
    const float* b2 = (const float*)d_in[7];
    const float* g2 = (const float*)d_in[8];
    const float* be2 = (const float*)d_in[9];
    const float* W3 = (const float*)d_in[10];
    const float* b3 = (const float*)d_in[11];
    const float* g3 = (const float*)d_in[12];
    const float* be3 = (const float*)d_in[13];
    const float* Wf = (const float*)d_in[14];
    const float* bf = (const float*)d_in[15];
    float* out = (float*)d_out;

    int nn = in_sizes[0] / 128;      // 100000
    int ee = in_sizes[1] / 2;        // 1600000
    const int* src = ei;
    const int* dst = ei + ee;

    int nb_e = (ee + 255) / 256;
    int nb_scan = (nn + 1023) / 1024;
    float invN = 1.0f / (float)nn;

    int gemm_blocks = (nn + 63) / 64;
    int gather_blocks = 1184;

    // ---- CSR build (counts/stats pre-zeroed: self-restoring invariants) ----
    hist_kernel<<<nb_e, 256>>>(dst, ee);
    scan1_kernel<<<nb_scan, 1024>>>(nn);
    scan3_kernel<<<nb_scan, 1024>>>(nn, ee, nb_scan);

    // ---- layer 1 (128 -> 64) ----
    gemm_scale_kernel<128, false, false><<<gemm_blocks, 256>>>(x, W1, nn);  // needs dinv only
    fill_kernel<<<nb_e, 256>>>(src, dst, ee);
    gather_kernel<<<gather_blocks, 256>>>(b1, nn);
    stats_final_kernel<<<1, 64>>>(g1, be1, invN);

    // ---- layer 2 (64 -> 64): BN1+GELU fused into X load ----
    gemm_scale_kernel<64, true, true><<<gemm_blocks, 256>>>(nullptr, W2, nn);
    gather_kernel<<<gather_blocks, 256>>>(b2, nn);
    stats_final_kernel<<<1, 64>>>(g2, be2, invN);

    // ---- layer 3 (64 -> 64): BN2+GELU fused into X load ----
    gemm_scale_kernel<64, true, true><<<gemm_blocks, 256>>>(nullptr, W3, nn);
    gather_kernel<<<gather_blocks, 256>>>(b3, nn);
    stats_final_kernel<<<1, 64>>>(g3, be3, invN);

    // ---- final classifier (64 -> 10): BN3+GELU fused into H load ----
    final_kernel<<<gemm_blocks, 128>>>(Wf, bf, out, nn);
}

// round 5
// speedup vs baseline: 1.0274x; 1.0274x over previous
#include <cuda_runtime.h>
#include <math.h>

#define NN_MAX 100000
#define EE_MAX 1600000
#define DH 64

// ---------------- device scratch ----------------
__device__ float g_tmp[NN_MAX * DH];   // fp32 messages: (act(X) @ W^T) * dinv
__device__ float g_h[NN_MAX * DH];     // layer activations (pre-BN, post-bias)
__device__ float g_dinv[NN_MAX];
__device__ int   g_counts[NN_MAX];     // zeroed by scan3 after use (self-restoring)
__device__ int   g_rowptr[NN_MAX + 1];
__device__ int   g_cursor[NN_MAX];
__device__ int   g_esrc[EE_MAX];
__device__ int   g_blocksums[128];
__device__ float g_sums[DH];           // zeroed by stats_final after use
__device__ float g_sumsq[DH];
__device__ float g_scale[DH];
__device__ float g_shift[DH];

__device__ __forceinline__ float gelu_f(float v) {
    return 0.5f * v * (1.0f + erff(v * 0.70710678118654752440f));
}

// ---------------- CSR build ----------------
__global__ void hist_kernel(const int* __restrict__ dst, int ee) {
    int e = blockIdx.x * blockDim.x + threadIdx.x;
    if (e < ee) atomicAdd(&g_counts[dst[e]], 1);
}

__global__ void scan1_kernel(int nn) {
    __shared__ int s[1024];
    int t = threadIdx.x;
    int i = blockIdx.x * 1024 + t;
    int c = (i < nn) ? g_counts[i] : 0;
    s[t] = c;
    __syncthreads();
    for (int off = 1; off < 1024; off <<= 1) {
        int v = (t >= off) ? s[t - off] : 0;
        __syncthreads();
        s[t] += v;
        __syncthreads();
    }
    if (i < nn) g_rowptr[i] = s[t];
    if (t == 1023) g_blocksums[blockIdx.x] = s[1023];
}

// merged scan2+scan3: finalize rowptr/cursor/dinv, zero counts for next call
__global__ void scan3_kernel(int nn, int ee, int nb) {
    __shared__ int bs[128];
    int t = threadIdx.x;
    if (t < 128) bs[t] = (t < nb) ? g_blocksums[t] : 0;
    __syncthreads();
    for (int off = 1; off < 128; off <<= 1) {
        int v = (t >= off && t < 128) ? bs[t - off] : 0;
        __syncthreads();
        if (t < 128) bs[t] += v;
        __syncthreads();
    }
    int base = (blockIdx.x == 0) ? 0 : bs[blockIdx.x - 1];

    int i = blockIdx.x * 1024 + t;
    if (i < nn) {
        int c = g_counts[i];
        g_counts[i] = 0;
        int excl = g_rowptr[i] - c + base;
        g_rowptr[i] = excl;
        g_cursor[i] = excl;
        g_dinv[i] = rsqrtf((float)(c + 1));  // +1 self loop
    }
    if (i == 0) g_rowptr[nn] = ee;
}

__global__ void fill_kernel(const int* __restrict__ src, const int* __restrict__ dst, int ee) {
    int e = blockIdx.x * blockDim.x + threadIdx.x;
    if (e < ee) {
        int pos = atomicAdd(&g_cursor[dst[e]], 1);
        g_esrc[pos] = src[e];
    }
}

// ---------------- GEMM: g_tmp[n,:] = (act(X)[n,:] @ W^T) * dinv[n] ----------------
// BM=128, BN=64, BK=32; 128 threads; 8x8 register tile -> 1 byte LDS / FMA.
template <int DIN, bool USE_GH, bool APPLY_ACT>
__global__ __launch_bounds__(128)
void gemm_scale_kernel(const float* __restrict__ Xin,
                       const float* __restrict__ W, int nn) {
    const float* __restrict__ X = USE_GH ? (const float*)g_h : Xin;

    __shared__ float Xs[32][132];  // [k][m], pad 4
    __shared__ float Ws[32][68];   // [k][j], pad 4
    __shared__ float s_sc[DH];
    __shared__ float s_sh[DH];

    int tid = threadIdx.x;
    int br = blockIdx.x * 128;
    int tx = tid & 7;    // col group: j0 = tx*8
    int ty = tid >> 3;   // row group: m0 = ty*8

    if (APPLY_ACT) {
        if (tid < DH) { s_sc[tid] = g_scale[tid]; s_sh[tid] = g_shift[tid]; }
        __syncthreads();
    }

    float acc[8][8];
#pragma unroll
    for (int i = 0; i < 8; i++)
#pragma unroll
        for (int j = 0; j < 8; j++) acc[i][j] = 0.0f;

    for (int kb = 0; kb < DIN; kb += 32) {
        // X tile: each thread owns one row (tid), 8 float4 along k, store transposed
        {
            int row = br + tid;
            bool ok = row < nn;
            const float* xr = X + (size_t)row * DIN + kb;
#pragma unroll
            for (int kk = 0; kk < 8; kk++) {
                float4 v = ok ? *(const float4*)(xr + kk * 4)
                              : make_float4(0.f, 0.f, 0.f, 0.f);
                if (APPLY_ACT && ok) {
                    int k0 = kb + kk * 4;
                    v.x = gelu_f(v.x * s_sc[k0 + 0] + s_sh[k0 + 0]);
                    v.y = gelu_f(v.y * s_sc[k0 + 1] + s_sh[k0 + 1]);
                    v.z = gelu_f(v.z * s_sc[k0 + 2] + s_sh[k0 + 2]);
                    v.w = gelu_f(v.w * s_sc[k0 + 3] + s_sh[k0 + 3]);
                }
                Xs[kk * 4 + 0][tid] = v.x;
                Xs[kk * 4 + 1][tid] = v.y;
                Xs[kk * 4 + 2][tid] = v.z;
                Xs[kk * 4 + 3][tid] = v.w;
            }
        }
        // W tile: thread -> j = tid&63, k-half = (tid>>6)*16, 4 float4
        {
            int j = tid & 63;
            int kh = (tid >> 6) * 16;
            const float* wr = W + (size_t)j * DIN + kb + kh;
#pragma unroll
            for (int kk = 0; kk < 4; kk++) {
                float4 v = *(const float4*)(wr + kk * 4);
                Ws[kh + kk * 4 + 0][j] = v.x;
                Ws[kh + kk * 4 + 1][j] = v.y;
                Ws[kh + kk * 4 + 2][j] = v.z;
                Ws[kh + kk * 4 + 3][j] = v.w;
            }
        }
        __syncthreads();

#pragma unroll 8
        for (int k = 0; k < 32; k++) {
            float4 a0 = *(const float4*)&Xs[k][ty * 8];
            float4 a1 = *(const float4*)&Xs[k][ty * 8 + 4];
            float4 b0 = *(const float4*)&Ws[k][tx * 8];
            float4 b1 = *(const float4*)&Ws[k][tx * 8 + 4];
            float a[8] = {a0.x, a0.y, a0.z, a0.w, a1.x, a1.y, a1.z, a1.w};
            float b[8] = {b0.x, b0.y, b0.z, b0.w, b1.x, b1.y, b1.z, b1.w};
#pragma unroll
            for (int i = 0; i < 8; i++)
#pragma unroll
                for (int j = 0; j < 8; j++) acc[i][j] += a[i] * b[j];
        }
        __syncthreads();
    }

#pragma unroll
    for (int i = 0; i < 8; i++) {
        int row = br + ty * 8 + i;
        if (row < nn) {
            float dv = g_dinv[row];
            float4 r0 = make_float4(acc[i][0] * dv, acc[i][1] * dv,
                                    acc[i][2] * dv, acc[i][3] * dv);
            float4 r1 = make_float4(acc[i][4] * dv, acc[i][5] * dv,
                                    acc[i][6] * dv, acc[i][7] * dv);
            *(float4*)&g_tmp[(size_t)row * DH + tx * 8] = r0;
            *(float4*)&g_tmp[(size_t)row * DH + tx * 8 + 4] = r1;
        }
    }
}

// ---------------- gather-aggregate + bias + BN stats ----------------
// warp per node; lane owns columns (2*lane, 2*lane+1) as float2; 8-wide unroll.
__global__ void gather_kernel(const float* __restrict__ bias, int nn) {
    __shared__ float ss[DH];
    __shared__ float sq[DH];
    int tid = threadIdx.x;
    if (tid < DH) { ss[tid] = 0.0f; sq[tid] = 0.0f; }
    __syncthreads();

    const float2* __restrict__ tmp2 = (const float2*)g_tmp;
    float2* __restrict__ h2 = (float2*)g_h;

    int lane = tid & 31;
    int warp = blockIdx.x * (blockDim.x >> 5) + (tid >> 5);
    int nwarps = gridDim.x * (blockDim.x >> 5);

    float bx = bias[2 * lane];
    float by = bias[2 * lane + 1];
    float s0 = 0.f, s1 = 0.f, q0 = 0.f, q1 = 0.f;

    for (int n = warp; n < nn; n += nwarps) {
        int st = g_rowptr[n];
        int en = g_rowptr[n + 1];
        float2 self = tmp2[n * 32 + lane];
        float ax = self.x, ay = self.y;
        int e = st;
        for (; e + 8 <= en; e += 8) {
            int idx[8];
#pragma unroll
            for (int u = 0; u < 8; u++) idx[u] = g_esrc[e + u];
            float2 v[8];
#pragma unroll
            for (int u = 0; u < 8; u++) v[u] = tmp2[idx[u] * 32 + lane];
            ax += ((v[0].x + v[1].x) + (v[2].x + v[3].x)) +
                  ((v[4].x + v[5].x) + (v[6].x + v[7].x));
            ay += ((v[0].y + v[1].y) + (v[2].y + v[3].y)) +
                  ((v[4].y + v[5].y) + (v[6].y + v[7].y));
        }
        for (; e < en; e++) {
            float2 v = tmp2[g_esrc[e] * 32 + lane];
            ax += v.x; ay += v.y;
        }
        float dv = g_dinv[n];
        float rx = ax * dv + bx;
        float ry = ay * dv + by;
        h2[n * 32 + lane] = make_float2(rx, ry);
        s0 += rx; q0 += rx * rx;
        s1 += ry; q1 += ry * ry;
    }

    atomicAdd(&ss[2 * lane], s0);
    atomicAdd(&ss[2 * lane + 1], s1);
    atomicAdd(&sq[2 * lane], q0);
    atomicAdd(&sq[2 * lane + 1], q1);
    __syncthreads();
    if (tid < DH) {
        atomicAdd(&g_sums[tid], ss[tid]);
        atomicAdd(&g_sumsq[tid], sq[tid]);
    }
}

// ---------------- BN stats -> scale/shift; re-zero stats ----------------
__global__ void stats_final_kernel(const float* __restrict__ gamma,
                                   const float* __restrict__ beta, float invN) {
    int j = threadIdx.x;  // 64 threads
    float mean = g_sums[j] * invN;
    float var = g_sumsq[j] * invN - mean * mean;
    float sc = gamma[j] * rsqrtf(var + 1e-5f);
    g_scale[j] = sc;
    g_shift[j] = beta[j] - mean * sc;
    g_sums[j] = 0.0f;
    g_sumsq[j] = 0.0f;
}

// ---------------- final: out = act(h) @ Wf^T + bf  (64 -> 10) ----------------
__global__ void final_kernel(const float* __restrict__ Wf, const float* __restrict__ bf,
                             float* __restrict__ out, int nn) {
    __shared__ float Hs[64][65];
    __shared__ float Ws[10][64];
    __shared__ float s_sc[DH];
    __shared__ float s_sh[DH];
    int tid = threadIdx.x;  // 128 threads
    int br = blockIdx.x * 64;

    if (tid < DH) { s_sc[tid] = g_scale[tid]; s_sh[tid] = g_shift[tid]; }
    __syncthreads();

    for (int idx = tid; idx < 64 * 64; idx += 128) {
        int n = idx >> 6, k = idx & 63;
        int row = br + n;
        float v = (row < nn) ? g_h[row * DH + k] : 0.0f;
        Hs[n][k] = gelu_f(v * s_sc[k] + s_sh[k]);
    }
    for (int idx = tid; idx < 640; idx += 128) {
        Ws[idx >> 6][idx & 63] = Wf[idx];
    }
    __syncthreads();

    int nl = tid & 63;
    int c0 = (tid >> 6) * 5;
    float acc[5];
#pragma unroll
    for (int c = 0; c < 5; c++) acc[c] = bf[c0 + c];
#pragma unroll 16
    for (int k = 0; k < 64; k++) {
        float hv = Hs[nl][k];
#pragma unroll
        for (int c = 0; c < 5; c++) acc[c] += hv * Ws[c0 + c][k];
    }
    int row = br + nl;
    if (row < nn) {
#pragma unroll
        for (int c = 0; c < 5; c++) out[row * 10 + c0 + c] = acc[c];
    }
}

// ---------------- host orchestration ----------------
extern "C" void kernel_launch(void* const* d_in, const int* in_sizes, int n_in,
                              void* d_out, int out_size) {
    const float* x  = (const float*)d_in[0];
    const int*   ei = (const int*)d_in[1];
    const float* W1 = (const float*)d_in[2];
    const float* b1 = (const float*)d_in[3];
    const float* g1 = (const float*)d_in[4];
    const float* be1 = (const float*)d_in[5];
    const float* W2 = (const float*)d_in[6];
    const float* b2 = (const float*)d_in[7];
    const float* g2 = (const float*)d_in[8];
    const float* be2 = (const float*)d_in[9];
    const float* W3 = (const float*)d_in[10];
    const float* b3 = (const float*)d_in[11];
    const float* g3 = (const float*)d_in[12];
    const float* be3 = (const float*)d_in[13];
    const float* Wf = (const float*)d_in[14];
    const float* bf = (const float*)d_in[15];
    float* out = (float*)d_out;

    int nn = in_sizes[0] / 128;      // 100000
    int ee = in_sizes[1] / 2;        // 1600000
    const int* src = ei;
    const int* dst = ei + ee;

    int nb_e = (ee + 255) / 256;
    int nb_scan = (nn + 1023) / 1024;
    float invN = 1.0f / (float)nn;

    int gemm_blocks = (nn + 127) / 128;
    int out_blocks = (nn + 63) / 64;
    int gather_blocks = 1184;

    // ---- CSR build (counts/stats pre-zeroed: self-restoring invariants) ----
    hist_kernel<<<nb_e, 256>>>(dst, ee);
    scan1_kernel<<<nb_scan, 1024>>>(nn);
    scan3_kernel<<<nb_scan, 1024>>>(nn, ee, nb_scan);

    // ---- layer 1 (128 -> 64) ----
    gemm_scale_kernel<128, false, false><<<gemm_blocks, 128>>>(x, W1, nn);
    fill_kernel<<<nb_e, 256>>>(src, dst, ee);
    gather_kernel<<<gather_blocks, 256>>>(b1, nn);
    stats_final_kernel<<<1, 64>>>(g1, be1, invN);

    // ---- layer 2 (64 -> 64): BN1+GELU fused into X load ----
    gemm_scale_kernel<64, true, true><<<gemm_blocks, 128>>>(nullptr, W2, nn);
    gather_kernel<<<gather_blocks, 256>>>(b2, nn);
    stats_final_kernel<<<1, 64>>>(g2, be2, invN);

    // ---- layer 3 (64 -> 64): BN2+GELU fused into X load ----
    gemm_scale_kernel<64, true, true><<<gemm_blocks, 128>>>(nullptr, W3, nn);
    gather_kernel<<<gather_blocks, 256>>>(b3, nn);
    stats_final_kernel<<<1, 64>>>(g3, be3, invN);

    // ---- final classifier (64 -> 10): BN3+GELU fused into H load ----
    final_kernel<<<out_blocks, 128>>>(Wf, bf, out, nn);
}

// round 6
// speedup vs baseline: 1.0428x; 1.0150x over previous
#include <cuda_runtime.h>
#include <math.h>

#define NN_MAX 100000
#define EE_MAX 1600000
#define DH 64

// ---------------- device scratch ----------------
__device__ float g_tmp[NN_MAX * DH];   // fp32 messages: (act(X) @ W^T) * dinv
__device__ float g_h[NN_MAX * DH];     // layer activations (pre-BN, post-bias)
__device__ float g_dinv[NN_MAX];
__device__ int   g_counts[NN_MAX];     // zeroed by scan3 after use (self-restoring)
__device__ int   g_rowptr[NN_MAX + 1];
__device__ int   g_cursor[NN_MAX];
__device__ int   g_esrc[EE_MAX];
__device__ int   g_blocksums[128];
__device__ float g_sums[DH];           // zeroed by stats_final after use
__device__ float g_sumsq[DH];
__device__ float g_scale[DH];
__device__ float g_shift[DH];

__device__ __forceinline__ float gelu_f(float v) {
    return 0.5f * v * (1.0f + erff(v * 0.70710678118654752440f));
}

// ---- packed f32x2 helpers (sm_103a FFMA2 path) ----
__device__ __forceinline__ unsigned long long pack2(float x, float y) {
    unsigned long long r;
    asm("mov.b64 %0, {%1, %2};" : "=l"(r) : "f"(x), "f"(y));
    return r;
}
__device__ __forceinline__ void fma2(unsigned long long& d, unsigned long long a,
                                     unsigned long long b) {
    asm("fma.rn.f32x2 %0, %1, %2, %0;" : "+l"(d) : "l"(a), "l"(b));
}
__device__ __forceinline__ float2 unpack2(unsigned long long v) {
    float2 f;
    asm("mov.b64 {%0, %1}, %2;" : "=f"(f.x), "=f"(f.y) : "l"(v));
    return f;
}

// ---------------- CSR build ----------------
__global__ void hist_kernel(const int* __restrict__ dst, int ee) {
    int e = blockIdx.x * blockDim.x + threadIdx.x;
    if (e < ee) atomicAdd(&g_counts[dst[e]], 1);
}

__global__ void scan1_kernel(int nn) {
    __shared__ int s[1024];
    int t = threadIdx.x;
    int i = blockIdx.x * 1024 + t;
    int c = (i < nn) ? g_counts[i] : 0;
    s[t] = c;
    __syncthreads();
    for (int off = 1; off < 1024; off <<= 1) {
        int v = (t >= off) ? s[t - off] : 0;
        __syncthreads();
        s[t] += v;
        __syncthreads();
    }
    if (i < nn) g_rowptr[i] = s[t];
    if (t == 1023) g_blocksums[blockIdx.x] = s[1023];
}

// merged scan2+scan3: finalize rowptr/cursor/dinv, zero counts for next call
__global__ void scan3_kernel(int nn, int ee, int nb) {
    __shared__ int bs[128];
    int t = threadIdx.x;
    if (t < 128) bs[t] = (t < nb) ? g_blocksums[t] : 0;
    __syncthreads();
    for (int off = 1; off < 128; off <<= 1) {
        int v = (t >= off && t < 128) ? bs[t - off] : 0;
        __syncthreads();
        if (t < 128) bs[t] += v;
        __syncthreads();
    }
    int base = (blockIdx.x == 0) ? 0 : bs[blockIdx.x - 1];

    int i = blockIdx.x * 1024 + t;
    if (i < nn) {
        int c = g_counts[i];
        g_counts[i] = 0;
        int excl = g_rowptr[i] - c + base;
        g_rowptr[i] = excl;
        g_cursor[i] = excl;
        g_dinv[i] = rsqrtf((float)(c + 1));  // +1 self loop
    }
    if (i == 0) g_rowptr[nn] = ee;
}

__global__ void fill_kernel(const int* __restrict__ src, const int* __restrict__ dst, int ee) {
    int e = blockIdx.x * blockDim.x + threadIdx.x;
    if (e < ee) {
        int pos = atomicAdd(&g_cursor[dst[e]], 1);
        g_esrc[pos] = src[e];
    }
}

// ---------------- GEMM: g_tmp[n,:] = (act(X)[n,:] @ W^T) * dinv[n] ----------------
// BM=128, BN=64, BK=32; 128 threads; 8x8 register tile; FFMA2 (fma.rn.f32x2)
// packed along j: 32 FFMA2 per k-step instead of 64 FFMA.
template <int DIN, bool USE_GH, bool APPLY_ACT>
__global__ __launch_bounds__(128)
void gemm_scale_kernel(const float* __restrict__ Xin,
                       const float* __restrict__ W, int nn) {
    const float* __restrict__ X = USE_GH ? (const float*)g_h : Xin;

    __shared__ float Xs[32][132];  // [k][m], pad 4
    __shared__ float Ws[32][68];   // [k][j], pad 4
    __shared__ float s_sc[DH];
    __shared__ float s_sh[DH];

    int tid = threadIdx.x;
    int br = blockIdx.x * 128;
    int tx = tid & 7;    // col group: j0 = tx*8
    int ty = tid >> 3;   // row group: m0 = ty*8

    if (APPLY_ACT) {
        if (tid < DH) { s_sc[tid] = g_scale[tid]; s_sh[tid] = g_shift[tid]; }
        __syncthreads();
    }

    unsigned long long accp[8][4];
#pragma unroll
    for (int i = 0; i < 8; i++)
#pragma unroll
        for (int j = 0; j < 4; j++) accp[i][j] = 0ULL;  // two packed 0.0f

    for (int kb = 0; kb < DIN; kb += 32) {
        // X tile: each thread owns one row (tid), 8 float4 along k, store transposed
        {
            int row = br + tid;
            bool ok = row < nn;
            const float* xr = X + (size_t)row * DIN + kb;
#pragma unroll
            for (int kk = 0; kk < 8; kk++) {
                float4 v = ok ? *(const float4*)(xr + kk * 4)
                              : make_float4(0.f, 0.f, 0.f, 0.f);
                if (APPLY_ACT && ok) {
                    int k0 = kb + kk * 4;
                    v.x = gelu_f(v.x * s_sc[k0 + 0] + s_sh[k0 + 0]);
                    v.y = gelu_f(v.y * s_sc[k0 + 1] + s_sh[k0 + 1]);
                    v.z = gelu_f(v.z * s_sc[k0 + 2] + s_sh[k0 + 2]);
                    v.w = gelu_f(v.w * s_sc[k0 + 3] + s_sh[k0 + 3]);
                }
                Xs[kk * 4 + 0][tid] = v.x;
                Xs[kk * 4 + 1][tid] = v.y;
                Xs[kk * 4 + 2][tid] = v.z;
                Xs[kk * 4 + 3][tid] = v.w;
            }
        }
        // W tile: thread -> j = tid&63, k-half = (tid>>6)*16, 4 float4
        {
            int j = tid & 63;
            int kh = (tid >> 6) * 16;
            const float* wr = W + (size_t)j * DIN + kb + kh;
#pragma unroll
            for (int kk = 0; kk < 4; kk++) {
                float4 v = *(const float4*)(wr + kk * 4);
                Ws[kh + kk * 4 + 0][j] = v.x;
                Ws[kh + kk * 4 + 1][j] = v.y;
                Ws[kh + kk * 4 + 2][j] = v.z;
                Ws[kh + kk * 4 + 3][j] = v.w;
            }
        }
        __syncthreads();

#pragma unroll 8
        for (int k = 0; k < 32; k++) {
            float4 a0 = *(const float4*)&Xs[k][ty * 8];
            float4 a1 = *(const float4*)&Xs[k][ty * 8 + 4];
            float4 b0 = *(const float4*)&Ws[k][tx * 8];
            float4 b1 = *(const float4*)&Ws[k][tx * 8 + 4];
            unsigned long long bp[4];
            bp[0] = pack2(b0.x, b0.y);
            bp[1] = pack2(b0.z, b0.w);
            bp[2] = pack2(b1.x, b1.y);
            bp[3] = pack2(b1.z, b1.w);
            float a[8] = {a0.x, a0.y, a0.z, a0.w, a1.x, a1.y, a1.z, a1.w};
#pragma unroll
            for (int i = 0; i < 8; i++) {
                unsigned long long ap = pack2(a[i], a[i]);
#pragma unroll
                for (int j = 0; j < 4; j++) fma2(accp[i][j], ap, bp[j]);
            }
        }
        __syncthreads();
    }

#pragma unroll
    for (int i = 0; i < 8; i++) {
        int row = br + ty * 8 + i;
        if (row < nn) {
            float dv = g_dinv[row];
            float2 p0 = unpack2(accp[i][0]);
            float2 p1 = unpack2(accp[i][1]);
            float2 p2 = unpack2(accp[i][2]);
            float2 p3 = unpack2(accp[i][3]);
            float4 r0 = make_float4(p0.x * dv, p0.y * dv, p1.x * dv, p1.y * dv);
            float4 r1 = make_float4(p2.x * dv, p2.y * dv, p3.x * dv, p3.y * dv);
            *(float4*)&g_tmp[(size_t)row * DH + tx * 8] = r0;
            *(float4*)&g_tmp[(size_t)row * DH + tx * 8 + 4] = r1;
        }
    }
}

// ---------------- gather-aggregate + bias + BN stats ----------------
// warp per node; lane owns columns (2*lane, 2*lane+1) as float2; 8-wide unroll.
__global__ void gather_kernel(const float* __restrict__ bias, int nn) {
    __shared__ float ss[DH];
    __shared__ float sq[DH];
    int tid = threadIdx.x;
    if (tid < DH) { ss[tid] = 0.0f; sq[tid] = 0.0f; }
    __syncthreads();

    const float2* __restrict__ tmp2 = (const float2*)g_tmp;
    float2* __restrict__ h2 = (float2*)g_h;

    int lane = tid & 31;
    int warp = blockIdx.x * (blockDim.x >> 5) + (tid >> 5);
    int nwarps = gridDim.x * (blockDim.x >> 5);

    float bx = bias[2 * lane];
    float by = bias[2 * lane + 1];
    float s0 = 0.f, s1 = 0.f, q0 = 0.f, q1 = 0.f;

    for (int n = warp; n < nn; n += nwarps) {
        int st = g_rowptr[n];
        int en = g_rowptr[n + 1];
        float2 self = tmp2[n * 32 + lane];
        float ax = self.x, ay = self.y;
        int e = st;
        for (; e + 8 <= en; e += 8) {
            int idx[8];
#pragma unroll
            for (int u = 0; u < 8; u++) idx[u] = g_esrc[e + u];
            float2 v[8];
#pragma unroll
            for (int u = 0; u < 8; u++) v[u] = tmp2[idx[u] * 32 + lane];
            ax += ((v[0].x + v[1].x) + (v[2].x + v[3].x)) +
                  ((v[4].x + v[5].x) + (v[6].x + v[7].x));
            ay += ((v[0].y + v[1].y) + (v[2].y + v[3].y)) +
                  ((v[4].y + v[5].y) + (v[6].y + v[7].y));
        }
        for (; e < en; e++) {
            float2 v = tmp2[g_esrc[e] * 32 + lane];
            ax += v.x; ay += v.y;
        }
        float dv = g_dinv[n];
        float rx = ax * dv + bx;
        float ry = ay * dv + by;
        h2[n * 32 + lane] = make_float2(rx, ry);
        s0 += rx; q0 += rx * rx;
        s1 += ry; q1 += ry * ry;
    }

    atomicAdd(&ss[2 * lane], s0);
    atomicAdd(&ss[2 * lane + 1], s1);
    atomicAdd(&sq[2 * lane], q0);
    atomicAdd(&sq[2 * lane + 1], q1);
    __syncthreads();
    if (tid < DH) {
        atomicAdd(&g_sums[tid], ss[tid]);
        atomicAdd(&g_sumsq[tid], sq[tid]);
    }
}

// ---------------- BN stats -> scale/shift; re-zero stats ----------------
__global__ void stats_final_kernel(const float* __restrict__ gamma,
                                   const float* __restrict__ beta, float invN) {
    int j = threadIdx.x;  // 64 threads
    float mean = g_sums[j] * invN;
    float var = g_sumsq[j] * invN - mean * mean;
    float sc = gamma[j] * rsqrtf(var + 1e-5f);
    g_scale[j] = sc;
    g_shift[j] = beta[j] - mean * sc;
    g_sums[j] = 0.0f;
    g_sumsq[j] = 0.0f;
}

// ---------------- final: out = act(h) @ Wf^T + bf  (64 -> 10) ----------------
__global__ void final_kernel(const float* __restrict__ Wf, const float* __restrict__ bf,
                             float* __restrict__ out, int nn) {
    __shared__ float Hs[64][65];
    __shared__ float Ws[10][64];
    __shared__ float s_sc[DH];
    __shared__ float s_sh[DH];
    int tid = threadIdx.x;  // 128 threads
    int br = blockIdx.x * 64;

    if (tid < DH) { s_sc[tid] = g_scale[tid]; s_sh[tid] = g_shift[tid]; }
    __syncthreads();

    for (int idx = tid; idx < 64 * 64; idx += 128) {
        int n = idx >> 6, k = idx & 63;
        int row = br + n;
        float v = (row < nn) ? g_h[row * DH + k] : 0.0f;
        Hs[n][k] = gelu_f(v * s_sc[k] + s_sh[k]);
    }
    for (int idx = tid; idx < 640; idx += 128) {
        Ws[idx >> 6][idx & 63] = Wf[idx];
    }
    __syncthreads();

    int nl = tid & 63;
    int c0 = (tid >> 6) * 5;
    float acc[5];
#pragma unroll
    for (int c = 0; c < 5; c++) acc[c] = bf[c0 + c];
#pragma unroll 16
    for (int k = 0; k < 64; k++) {
        float hv = Hs[nl][k];
#pragma unroll
        for (int c = 0; c < 5; c++) acc[c] += hv * Ws[c0 + c][k];
    }
    int row = br + nl;
    if (row < nn) {
#pragma unroll
        for (int c = 0; c < 5; c++) out[row * 10 + c0 + c] = acc[c];
    }
}

// ---------------- host orchestration ----------------
extern "C" void kernel_launch(void* const* d_in, const int* in_sizes, int n_in,
                              void* d_out, int out_size) {
    const float* x  = (const float*)d_in[0];
    const int*   ei = (const int*)d_in[1];
    const float* W1 = (const float*)d_in[2];
    const float* b1 = (const float*)d_in[3];
    const float* g1 = (const float*)d_in[4];
    const float* be1 = (const float*)d_in[5];
    const float* W2 = (const float*)d_in[6];
    const float* b2 = (const float*)d_in[7];
    const float* g2 = (const float*)d_in[8];
    const float* be2 = (const float*)d_in[9];
    const float* W3 = (const float*)d_in[10];
    const float* b3 = (const float*)d_in[11];
    const float* g3 = (const float*)d_in[12];
    const float* be3 = (const float*)d_in[13];
    const float* Wf = (const float*)d_in[14];
    const float* bf = (const float*)d_in[15];
    float* out = (float*)d_out;

    int nn = in_sizes[0] / 128;      // 100000
    int ee = in_sizes[1] / 2;        // 1600000
    const int* src = ei;
    const int* dst = ei + ee;

    int nb_e = (ee + 255) / 256;
    int nb_scan = (nn + 1023) / 1024;
    float invN = 1.0f / (float)nn;

    int gemm_blocks = (nn + 127) / 128;
    int out_blocks = (nn + 63) / 64;
    int gather_blocks = 1184;

    // ---- CSR build (counts/stats pre-zeroed: self-restoring invariants) ----
    hist_kernel<<<nb_e, 256>>>(dst, ee);
    scan1_kernel<<<nb_scan, 1024>>>(nn);
    scan3_kernel<<<nb_scan, 1024>>>(nn, ee, nb_scan);

    // ---- layer 1 (128 -> 64) ----
    gemm_scale_kernel<128, false, false><<<gemm_blocks, 128>>>(x, W1, nn);
    fill_kernel<<<nb_e, 256>>>(src, dst, ee);
    gather_kernel<<<gather_blocks, 256>>>(b1, nn);
    stats_final_kernel<<<1, 64>>>(g1, be1, invN);

    // ---- layer 2 (64 -> 64): BN1+GELU fused into X load ----
    gemm_scale_kernel<64, true, true><<<gemm_blocks, 128>>>(nullptr, W2, nn);
    gather_kernel<<<gather_blocks, 256>>>(b2, nn);
    stats_final_kernel<<<1, 64>>>(g2, be2, invN);

    // ---- layer 3 (64 -> 64): BN2+GELU fused into X load ----
    gemm_scale_kernel<64, true, true><<<gemm_blocks, 128>>>(nullptr, W3, nn);
    gather_kernel<<<gather_blocks, 256>>>(b3, nn);
    stats_final_kernel<<<1, 64>>>(g3, be3, invN);

    // ---- final classifier (64 -> 10): BN3+GELU fused into H load ----
    final_kernel<<<out_blocks, 128>>>(Wf, bf, out, nn);
}